// round 10
// baseline (speedup 1.0000x reference)
#include <cuda_runtime.h>
#include <cuda_fp16.h>
#include <math.h>
#include <stdint.h>

#define DDIM   2048
#define NEXP   64
#define NCOL   128            // router(64) | noise(64) output columns
#define TM     64             // tokens per CTA
#define KC     64             // K elems per chunk
#define NC     (DDIM / KC)    // 32 chunks
#define NTHREADS 192          // 4 consumer warps + 2 producer warps
#define NPROD  64
#define NCONS_THREADS 128
#define AS     133
#define US     65
#define WSCALE 2048.0f
#define INVSCALE (1.0f / 2048.0f)
#define TAU    4e-3f          // margin below which a token gets exact recompute
#define MAXFIX 16384

#define RSTRIDE 144                    // smem row stride bytes (128B data + 16B pad)
#define A_PL    (TM  * RSTRIDE)        // 9216  B per A plane (64 rows)
#define B_PL    (NCOL * RSTRIDE)       // 18432 B (128 rows)
#define STAGE_A (2 * A_PL)             // 18432 (x0, x1 planes)
#define STAGE_BYTES (STAGE_A + B_PL)   // 36864
#define STAGES  3
#define SM_RING 1024
#define SMEM_BYTES (SM_RING + STAGES * STAGE_BYTES)   // 111616 (x2 CTAs/SM)

// w0 plane only, scaled by 2048 (router rows 0..63, noise rows 64..127)
__device__ __half g_wp[NCOL][DDIM];
__device__ float  g_vals[16384 * NEXP];   // approx noisy values (4 MB)
__device__ int    g_fix_list[MAXFIX];
__device__ int    g_fix_count;

// ---------------- helpers ----------------
__device__ __forceinline__ uint32_t smem_u32(const void* p) {
    uint32_t a;
    asm("{ .reg .u64 t; cvta.to.shared.u64 t, %1; cvt.u32.u64 %0, t; }" : "=r"(a) : "l"(p));
    return a;
}
__device__ __forceinline__ void mbar_init(uint32_t a, uint32_t cnt) {
    asm volatile("mbarrier.init.shared.b64 [%0], %1;" :: "r"(a), "r"(cnt) : "memory");
}
__device__ __forceinline__ void mbar_arrive(uint32_t a) {
    asm volatile("mbarrier.arrive.shared.b64 _, [%0];" :: "r"(a) : "memory");
}
__device__ __forceinline__ void mbar_wait(uint32_t a, uint32_t parity) {
    asm volatile(
        "{\n\t.reg .pred P1;\n\t"
        "W%=:\n\t"
        "mbarrier.try_wait.parity.acquire.cta.shared::cta.b64 P1, [%0], %1, 0x989680;\n\t"
        "@P1 bra.uni D%=;\n\t"
        "bra.uni W%=;\n\t"
        "D%=:\n\t}"
        :: "r"(a), "r"(parity) : "memory");
}
__device__ __forceinline__ void split2(float lo, float hi, uint32_t& u0, uint32_t& u1) {
    __half2 h0 = __floats2half2_rn(lo, hi);
    float l0 = __half2float(__low2half(h0));
    float hh = __half2float(__high2half(h0));
    __half2 h1 = __floats2half2_rn(lo - l0, hi - hh);
    u0 = *reinterpret_cast<uint32_t*>(&h0);
    u1 = *reinterpret_cast<uint32_t*>(&h1);
}
#define LDSM4(r, a) \
    asm volatile("ldmatrix.sync.aligned.m8n8.x4.shared.b16 {%0,%1,%2,%3}, [%4];" \
        : "=r"((r)[0]), "=r"((r)[1]), "=r"((r)[2]), "=r"((r)[3]) : "r"(a))
#define MMA16816(d, a, b) \
    asm volatile("mma.sync.aligned.m16n8k16.row.col.f32.f16.f16.f32 " \
        "{%0,%1,%2,%3}, {%4,%5,%6,%7}, {%8,%9}, {%0,%1,%2,%3};" \
        : "+f"((d)[0]), "+f"((d)[1]), "+f"((d)[2]), "+f"((d)[3]) \
        : "r"((a)[0]), "r"((a)[1]), "r"((a)[2]), "r"((a)[3]), "r"((b)[0]), "r"((b)[1]))
#define CPASYNC16(dst, src) \
    asm volatile("cp.async.cg.shared.global [%0], [%1], 16;" :: "r"(dst), "l"(src) : "memory")

// ---------------- prep: w0 plane + zero fix counter ----------------
__global__ void prep_w_kernel(const float* __restrict__ rw, const float* __restrict__ nw) {
    int idx = blockIdx.x * blockDim.x + threadIdx.x;
    if (idx == 0) g_fix_count = 0;
    int r = idx >> 11, k = idx & 2047;
    float v = WSCALE * ((r < NEXP) ? rw[r * DDIM + k] : nw[(r - NEXP) * DDIM + k]);
    g_wp[r][k] = __float2half_rn(v);
}

// ---------------- main fused kernel ----------------
extern __shared__ char smem[];

__global__ __launch_bounds__(NTHREADS, 2)
void router_hmma_kernel(const float* __restrict__ x,
                        const float* __restrict__ rb,
                        const float* __restrict__ nb,
                        const float* __restrict__ u,
                        float* __restrict__ out,
                        int M)
{
    const int tid  = threadIdx.x;
    const int wid  = tid >> 5;
    const int lane = tid & 31;
    const int m0   = blockIdx.x * TM;
    const uint32_t sb = smem_u32(smem);

    if (tid == 0) {
#pragma unroll
        for (int s = 0; s < STAGES; s++) {
            mbar_init(sb + s * 16, NPROD);             // full
            mbar_init(sb + s * 16 + 8, NCONS_THREADS); // empty
        }
    }
    __syncthreads();

    if (wid >= 4) {
        // ================= PRODUCER (warps 4-5, 64 threads) =================
        const int ptid = tid - NCONS_THREADS;
        float4 av[16];
        for (int c = 0; c < NC; c++) {
            const int s = c % STAGES;
            const uint32_t aA = sb + SM_RING + s * STAGE_BYTES;
            const uint32_t aB = aA + STAGE_A;
            mbar_wait(sb + s * 16 + 8, ((c / STAGES) & 1) ^ 1);   // wait empty

            // A: 64 rows x 16 float4, all LDGs upfront
#pragma unroll
            for (int i = 0; i < 16; i++) {
                int q = ptid + i * NPROD;
                int row = q >> 4, kq = q & 15;
                av[i] = *(const float4*)(x + (size_t)(m0 + row) * DDIM + c * KC + kq * 4);
            }
            // B: 1 plane x 128 rows x 8 16B-cells = 1024 cells, 16/thread
#pragma unroll
            for (int i = 0; i < 16; i++) {
                int q = ptid + i * NPROD;
                int row = q >> 3, cg = q & 7;
                uint32_t dst = aB + row * RSTRIDE + cg * 16;
                CPASYNC16(dst, &g_wp[row][c * KC + cg * 8]);
            }
            asm volatile("cp.async.commit_group;" ::: "memory");

#pragma unroll
            for (int i = 0; i < 16; i++) {
                int q = ptid + i * NPROD;
                int row = q >> 4, kq = q & 15;
                uint32_t p0a, p1a, p0b, p1b;
                split2(av[i].x, av[i].y, p0a, p1a);
                split2(av[i].z, av[i].w, p0b, p1b);
                uint32_t base = (aA - sb) + row * RSTRIDE + kq * 8;
                *(uint2*)(smem + base + 0 * A_PL) = make_uint2(p0a, p0b);
                *(uint2*)(smem + base + 1 * A_PL) = make_uint2(p1a, p1b);
            }
            asm volatile("cp.async.wait_group 0;" ::: "memory");
            mbar_arrive(sb + s * 16);                              // full
        }
    } else {
        // ================= CONSUMER (warps 0-3, 128 threads) =================
        const int wm = wid >> 1;   // 0..1 -> 32-row slab
        const int wn = wid & 1;    // 0..1 -> 64-col slab

        uint32_t aoff[2], boff[4];
#pragma unroll
        for (int mt = 0; mt < 2; mt++) {
            int row = wm * 32 + mt * 16 + (lane & 7) + 8 * ((lane >> 3) & 1);
            aoff[mt] = (uint32_t)(row * RSTRIDE + 16 * ((lane >> 4) & 1));
        }
#pragma unroll
        for (int ntp = 0; ntp < 4; ntp++) {
            int row = wn * 64 + ntp * 16 + ((lane >> 4) & 1) * 8 + (lane & 7);
            boff[ntp] = (uint32_t)(row * RSTRIDE + 16 * ((lane >> 3) & 1));
        }

        float acc[2][8][4];
#pragma unroll
        for (int mt = 0; mt < 2; mt++)
#pragma unroll
            for (int nt = 0; nt < 8; nt++)
#pragma unroll
                for (int e = 0; e < 4; e++) acc[mt][nt][e] = 0.f;

        for (int c = 0; c < NC; c++) {
            const int s = c % STAGES;
            const uint32_t aA = sb + SM_RING + s * STAGE_BYTES;
            const uint32_t aB = aA + STAGE_A;
            mbar_wait(sb + s * 16, (c / STAGES) & 1);              // wait full

#pragma unroll
            for (int ks = 0; ks < 4; ks++) {
                uint32_t a0[2][4], a1[2][4], b[8][2];
#pragma unroll
                for (int mt = 0; mt < 2; mt++) {
                    LDSM4(a0[mt], aA + 0 * A_PL + ks * 32 + aoff[mt]);
                    LDSM4(a1[mt], aA + 1 * A_PL + ks * 32 + aoff[mt]);
                }
#pragma unroll
                for (int ntp = 0; ntp < 4; ntp++) {
                    uint32_t t4[4];
                    LDSM4(t4, aB + ks * 32 + boff[ntp]);
                    b[2 * ntp][0] = t4[0]; b[2 * ntp][1] = t4[1];
                    b[2 * ntp + 1][0] = t4[2]; b[2 * ntp + 1][1] = t4[3];
                }
                // q00: x0*w0
#pragma unroll
                for (int mt = 0; mt < 2; mt++)
#pragma unroll
                    for (int nt = 0; nt < 8; nt++)
                        MMA16816(acc[mt][nt], a0[mt], b[nt]);
                // q10: x1*w0
#pragma unroll
                for (int mt = 0; mt < 2; mt++)
#pragma unroll
                    for (int nt = 0; nt < 8; nt++)
                        MMA16816(acc[mt][nt], a1[mt], b[nt]);
            }
            mbar_arrive(sb + s * 16 + 8);                          // arrive empty
        }

        __syncthreads();   // ring dead, safe to reuse
        float* acc_s = (float*)(smem + SM_RING);
#pragma unroll
        for (int mt = 0; mt < 2; mt++)
#pragma unroll
            for (int nt = 0; nt < 8; nt++) {
                int r   = wm * 32 + mt * 16 + (lane >> 2);
                int col = wn * 64 + nt * 8 + (lane & 3) * 2;
                acc_s[r * AS + col]           = acc[mt][nt][0];
                acc_s[r * AS + col + 1]       = acc[mt][nt][1];
                acc_s[(r + 8) * AS + col]     = acc[mt][nt][2];
                acc_s[(r + 8) * AS + col + 1] = acc[mt][nt][3];
            }
    }
    if (wid >= 4) __syncthreads();   // producers join the same barrier

    float* acc_s = (float*)(smem + SM_RING);
    float* su    = acc_s + TM * AS;
    {
        const float* ug = u + (size_t)m0 * NEXP;
        for (int q = tid; q < TM * NEXP; q += NTHREADS) {
            int r = q >> 6, cn = q & 63;
            su[r * US + cn] = ug[(size_t)r * NEXP + cn];
        }
    }
    __syncthreads();

    // ---- per-token epilogue: approx noisy values, top-3, margin check ----
    if (tid < TM) {
        const int m = m0 + tid;
        float* row = acc_s + tid * AS;
        float* urow = su + tid * US;

        float v1 = -INFINITY, v2 = -INFINITY, v3 = -INFINITY;
        int i1 = 0, i2 = 0;
        for (int e = 0; e < NEXP; e++) {
            float lg = row[e] * INVSCALE + rb[e];
            float nz = row[NEXP + e] * INVSCALE + nb[e];
            float sp = fmaxf(nz, 0.f) + log1pf(expf(-fabsf(nz)));
            float uu = urow[e];
            float nv = lg + sp * uu;
            urow[e] = nv;                    // stash approx value (u consumed)
            if (nv > v1)      { v3 = v2; v2 = v1; i2 = i1; v1 = nv; i1 = e; }
            else if (nv > v2) { v3 = v2; v2 = nv; i2 = e; }
            else if (nv > v3) { v3 = nv; }
        }
        float e2 = expf(v2 - v1);
        float den = 1.f + e2;
        float p1 = 1.f / den;
        float p2 = e2 / den;

        for (int e = 0; e < NEXP; e++) row[e] = 0.f;
        row[i1] = p1;
        row[i2] = p2;

        float* oid = out + (size_t)M * NEXP;
        oid[(size_t)m * 2 + 0] = (float)i1;
        oid[(size_t)m * 2 + 1] = (float)i2;

        if ((v1 - v2 < TAU) || (v2 - v3 < TAU)) {
            int pos = atomicAdd(&g_fix_count, 1);
            if (pos < MAXFIX) g_fix_list[pos] = m;
        }
    }
    __syncthreads();

    // approx values -> gmem (coalesced), for the correction pass
    for (int q = tid; q < TM * NEXP; q += NTHREADS) {
        int r = q >> 6, e = q & 63;
        g_vals[(size_t)(m0 + r) * NEXP + e] = su[r * US + e];
    }

    // coalesced probability writeback
    for (int t = tid; t < TM * (NEXP / 4); t += NTHREADS) {
        int r = t >> 4;
        int c4 = (t & 15) * 4;
        float4 v = make_float4(acc_s[r * AS + c4 + 0],
                               acc_s[r * AS + c4 + 1],
                               acc_s[r * AS + c4 + 2],
                               acc_s[r * AS + c4 + 3]);
        *(float4*)(out + (size_t)(m0 + r) * NEXP + c4) = v;
    }
}

// ---------------- correction: exact fp32 recompute for flagged tokens ----------------
__global__ __launch_bounds__(64, 8)
void fix_kernel(const float* __restrict__ x,
                const float* __restrict__ rw,
                const float* __restrict__ rb,
                const float* __restrict__ nw,
                const float* __restrict__ nb,
                const float* __restrict__ u,
                float* __restrict__ out,
                int M)
{
    __shared__ float sx[DDIM];
    __shared__ float sv[NEXP];
    __shared__ float s_cut, s_p1, s_p2;
    __shared__ int   s_i1, s_i2;

    const int t = threadIdx.x;  // 64 threads
    int n = g_fix_count;
    if (n > MAXFIX) n = MAXFIX;

    for (int i = blockIdx.x; i < n; i += gridDim.x) {
        const int m = g_fix_list[i];

        // stage x row
        for (int k = t; k < DDIM / 4; k += 64)
            ((float4*)sx)[k] = ((const float4*)(x + (size_t)m * DDIM))[k];
        float av = g_vals[(size_t)m * NEXP + t];
        sv[t] = av;
        __syncthreads();

        if (t == 0) {
            float b1 = -INFINITY, b2 = -INFINITY;
            for (int e = 0; e < NEXP; e++) {
                float v = sv[e];
                if (v > b1) { b2 = b1; b1 = v; }
                else if (v > b2) { b2 = v; }
            }
            s_cut = b2 - TAU;
        }
        __syncthreads();

        float nv = -INFINITY;
        if (av >= s_cut) {
            const float* wr = rw + (size_t)t * DDIM;
            const float* wn = nw + (size_t)t * DDIM;
            float d0 = 0.f, d1 = 0.f, d2 = 0.f, d3 = 0.f;
            float n0 = 0.f, n1 = 0.f, n2 = 0.f, n3 = 0.f;
            for (int k = 0; k < DDIM; k += 4) {
                float4 xv = *(const float4*)(sx + k);
                float4 rv = *(const float4*)(wr + k);
                float4 nvv = *(const float4*)(wn + k);
                d0 += xv.x * rv.x;  d1 += xv.y * rv.y;
                d2 += xv.z * rv.z;  d3 += xv.w * rv.w;
                n0 += xv.x * nvv.x; n1 += xv.y * nvv.y;
                n2 += xv.z * nvv.z; n3 += xv.w * nvv.w;
            }
            float lg = (d0 + d1) + (d2 + d3) + rb[t];
            float nz = (n0 + n1) + (n2 + n3) + nb[t];
            float sp = fmaxf(nz, 0.f) + log1pf(expf(-fabsf(nz)));
            nv = lg + sp * u[(size_t)m * NEXP + t];
        }
        sv[t] = nv;
        __syncthreads();

        if (t == 0) {
            float v1 = -INFINITY, v2 = -INFINITY;
            int i1 = 0, i2 = 0;
            for (int e = 0; e < NEXP; e++) {
                float v = sv[e];
                if (v > v1)      { v2 = v1; i2 = i1; v1 = v; i1 = e; }
                else if (v > v2) { v2 = v; i2 = e; }
            }
            float e2 = expf(v2 - v1);
            float den = 1.f + e2;
            s_p1 = 1.f / den;
            s_p2 = e2 / den;
            s_i1 = i1;
            s_i2 = i2;
        }
        __syncthreads();

        out[(size_t)m * NEXP + t] = (t == s_i1) ? s_p1 : ((t == s_i2) ? s_p2 : 0.f);
        if (t == 0) {
            float* oid = out + (size_t)M * NEXP;
            oid[(size_t)m * 2 + 0] = (float)s_i1;
            oid[(size_t)m * 2 + 1] = (float)s_i2;
        }
        __syncthreads();
    }
}

extern "C" void kernel_launch(void* const* d_in, const int* in_sizes, int n_in,
                              void* d_out, int out_size)
{
    const float* x  = (const float*)d_in[0];
    const float* rw = (const float*)d_in[1];
    const float* rb = (const float*)d_in[2];
    const float* nw = (const float*)d_in[3];
    const float* nb = (const float*)d_in[4];
    const float* u  = (const float*)d_in[5];

    const int M = in_sizes[0] / DDIM;  // 16384

    static bool attr_set = false;
    if (!attr_set) {
        cudaFuncSetAttribute(router_hmma_kernel,
                             cudaFuncAttributeMaxDynamicSharedMemorySize,
                             SMEM_BYTES);
        attr_set = true;
    }

    prep_w_kernel<<<(NCOL * DDIM) / 256, 256>>>(rw, nw);
    router_hmma_kernel<<<M / TM, NTHREADS, SMEM_BYTES>>>(x, rb, nb, u, (float*)d_out, M);
    fix_kernel<<<256, 64>>>(x, rw, rb, nw, nb, u, (float*)d_out, M);
}

// round 11
// speedup vs baseline: 1.1050x; 1.1050x over previous
#include <cuda_runtime.h>
#include <cuda_fp16.h>
#include <math.h>
#include <stdint.h>

#define DDIM   2048
#define NEXP   64
#define NCOL   128            // router(64) | noise(64) output columns
#define TM     64             // tokens per CTA
#define KC     64             // K elems per chunk
#define NC     (DDIM / KC)    // 32 chunks
#define NTHREADS 192          // 4 consumer warps + 2 producer warps
#define NPROD  64
#define NCONS_THREADS 128
#define AS     133
#define US     65
#define WSCALE 2048.0f
#define INVSCALE (1.0f / 2048.0f)

#define RSTRIDE 144                    // smem row stride bytes (128B data + 16B pad)
#define A_PL    (TM  * RSTRIDE)        // 9216  B per A plane (64 rows)
#define B_PL    (NCOL * RSTRIDE)       // 18432 B per B plane (128 rows)
#define STAGE_A (2 * A_PL)             // 18432
#define STAGE_BYTES (STAGE_A + 2 * B_PL)   // 55296
#define STAGES  2
#define SM_RING 1024
#define SM_SU   (SM_RING + STAGES * STAGE_BYTES)      // 111616: u tile above ring
#define SMEM_BYTES (SM_SU + TM * US * 4)              // 128256... check below
// SM_SU = 1024 + 110592 = 111616; + 64*65*4 = 16640 -> 128256 (x2 > 227KB!) -- shrink:
// use STAGES=2 with KC=64: ring = 2*55296 = 110592. Too big for su on top at 2 CTAs/SM.
// Fix: overlap su with stage-0 A region is unsafe; instead place su in the last
// 16.6KB of stage 1's B plane-1 area is unsafe too. Solution: producers prefetch u
// into REGISTERS and store to smem after the final __syncthreads barrier region
// becomes free. Simpler: keep ring at 110592 and put su at top only if it fits:
// 111616+16640=128256 -> 2 CTAs = 256512 > 232448 limit. So: revert su placement,
// load u AFTER loop into ring area (as r7), but via producers DURING the tail:
// producers finish chunks ~2600 cyc before consumers; they stash u in registers
// then store after the joint __syncthreads. Register stash: 16384B/64thr = 64 floats
// = 64 regs/thread. Feasible (producer regs low). See code.
#undef SM_SU
#undef SMEM_BYTES
#define SMEM_BYTES (SM_RING + STAGES * STAGE_BYTES)   // 111616 (x2 CTAs/SM = 223232)

// ---------------- helpers ----------------
__device__ __forceinline__ uint32_t smem_u32(const void* p) {
    uint32_t a;
    asm("{ .reg .u64 t; cvta.to.shared.u64 t, %1; cvt.u32.u64 %0, t; }" : "=r"(a) : "l"(p));
    return a;
}
__device__ __forceinline__ void mbar_init(uint32_t a, uint32_t cnt) {
    asm volatile("mbarrier.init.shared.b64 [%0], %1;" :: "r"(a), "r"(cnt) : "memory");
}
__device__ __forceinline__ void mbar_arrive(uint32_t a) {
    asm volatile("mbarrier.arrive.shared.b64 _, [%0];" :: "r"(a) : "memory");
}
__device__ __forceinline__ void mbar_wait(uint32_t a, uint32_t parity) {
    asm volatile(
        "{\n\t.reg .pred P1;\n\t"
        "W%=:\n\t"
        "mbarrier.try_wait.parity.acquire.cta.shared::cta.b64 P1, [%0], %1, 0x989680;\n\t"
        "@P1 bra.uni D%=;\n\t"
        "bra.uni W%=;\n\t"
        "D%=:\n\t}"
        :: "r"(a), "r"(parity) : "memory");
}
// 2-way fp16 split of a float pair (lo,hi) -> 2 f16x2 regs
__device__ __forceinline__ void split2(float lo, float hi, uint32_t& u0, uint32_t& u1) {
    __half2 h0 = __floats2half2_rn(lo, hi);
    float l0 = __half2float(__low2half(h0));
    float hh = __half2float(__high2half(h0));
    __half2 h1 = __floats2half2_rn(lo - l0, hi - hh);
    u0 = *reinterpret_cast<uint32_t*>(&h0);
    u1 = *reinterpret_cast<uint32_t*>(&h1);
}
#define LDSM4(r, a) \
    asm volatile("ldmatrix.sync.aligned.m8n8.x4.shared.b16 {%0,%1,%2,%3}, [%4];" \
        : "=r"((r)[0]), "=r"((r)[1]), "=r"((r)[2]), "=r"((r)[3]) : "r"(a))
#define MMA16816(d, a, b) \
    asm volatile("mma.sync.aligned.m16n8k16.row.col.f32.f16.f16.f32 " \
        "{%0,%1,%2,%3}, {%4,%5,%6,%7}, {%8,%9}, {%0,%1,%2,%3};" \
        : "+f"((d)[0]), "+f"((d)[1]), "+f"((d)[2]), "+f"((d)[3]) \
        : "r"((a)[0]), "r"((a)[1]), "r"((a)[2]), "r"((a)[3]), "r"((b)[0]), "r"((b)[1]))

// ---------------- main fused kernel (single launch) ----------------
extern __shared__ char smem[];

__global__ __launch_bounds__(NTHREADS, 2)
void router_hmma_kernel(const float* __restrict__ x,
                        const float* __restrict__ rw,
                        const float* __restrict__ rb,
                        const float* __restrict__ nw,
                        const float* __restrict__ nb,
                        const float* __restrict__ u,
                        float* __restrict__ out,
                        int M)
{
    const int tid  = threadIdx.x;
    const int wid  = tid >> 5;
    const int lane = tid & 31;
    const int m0   = blockIdx.x * TM;
    const uint32_t sb = smem_u32(smem);

    if (tid == 0) {
#pragma unroll
        for (int s = 0; s < STAGES; s++) {
            mbar_init(sb + s * 16, NPROD);             // full: 64 producer arrivals
            mbar_init(sb + s * 16 + 8, NCONS_THREADS); // empty: 128 consumer arrivals
        }
    }
    __syncthreads();

    float ureg[64];   // producer-only u stash (dead in consumers)

    if (wid >= 4) {
        // ================= PRODUCER (warps 4-5, 64 threads) =================
        const int ptid = tid - NCONS_THREADS;
        float4 av[16];
        for (int c = 0; c < NC; c++) {
            const int s = c & 1;
            const uint32_t aA = sb + SM_RING + s * STAGE_BYTES;
            mbar_wait(sb + s * 16 + 8, ((c >> 1) & 1) ^ 1);       // wait empty

            // A: 64 rows x 16 float4, all LDGs upfront
#pragma unroll
            for (int i = 0; i < 16; i++) {
                int q = ptid + i * NPROD;
                int row = q >> 4, kq = q & 15;
                av[i] = *(const float4*)(x + (size_t)(m0 + row) * DDIM + c * KC + kq * 4);
            }
#pragma unroll
            for (int i = 0; i < 16; i++) {
                int q = ptid + i * NPROD;
                int row = q >> 4, kq = q & 15;
                uint32_t p0a, p1a, p0b, p1b;
                split2(av[i].x, av[i].y, p0a, p1a);
                split2(av[i].z, av[i].w, p0b, p1b);
                uint32_t base = (aA - sb) + row * RSTRIDE + kq * 8;
                *(uint2*)(smem + base + 0 * A_PL) = make_uint2(p0a, p0b);
                *(uint2*)(smem + base + 1 * A_PL) = make_uint2(p1a, p1b);
            }

            // B: inline fp32 W load + scale + split (replaces prep kernel).
            // 128 rows x 16 float4 = 2048 cells, 32/thread, two batches of 16.
            const uint32_t bB = (aA - sb) + STAGE_A;
#pragma unroll
            for (int h = 0; h < 2; h++) {
                float4 wv[16];
#pragma unroll
                for (int i = 0; i < 16; i++) {
                    int q = ptid + (h * 16 + i) * NPROD;
                    int row = q >> 4, kq = q & 15;
                    const float* wsrc = (row < NEXP)
                        ? (rw + (size_t)row * DDIM)
                        : (nw + (size_t)(row - NEXP) * DDIM);
                    wv[i] = *(const float4*)(wsrc + c * KC + kq * 4);
                }
#pragma unroll
                for (int i = 0; i < 16; i++) {
                    int q = ptid + (h * 16 + i) * NPROD;
                    int row = q >> 4, kq = q & 15;
                    uint32_t p0a, p1a, p0b, p1b;
                    split2(wv[i].x * WSCALE, wv[i].y * WSCALE, p0a, p1a);
                    split2(wv[i].z * WSCALE, wv[i].w * WSCALE, p0b, p1b);
                    uint32_t base = bB + row * RSTRIDE + kq * 8;
                    *(uint2*)(smem + base + 0 * B_PL) = make_uint2(p0a, p0b);
                    *(uint2*)(smem + base + 1 * B_PL) = make_uint2(p1a, p1b);
                }
            }
            mbar_arrive(sb + s * 16);                              // full
        }
        // tail: prefetch u tile into registers while consumers finish MMAs
        // 64 tokens x 64 experts = 4096 floats, 64 floats/thread (one token each)
        {
            const float* ur = u + (size_t)(m0 + ptid) * NEXP;
#pragma unroll
            for (int e = 0; e < 64; e++) ureg[e] = ur[e];
        }
    } else {
        // ================= CONSUMER (warps 0-3, 128 threads) =================
        const int wm = wid >> 1;   // 0..1 -> 32-row slab
        const int wn = wid & 1;    // 0..1 -> 64-col slab

        uint32_t aoff[2], boff[4];
#pragma unroll
        for (int mt = 0; mt < 2; mt++) {
            int row = wm * 32 + mt * 16 + (lane & 7) + 8 * ((lane >> 3) & 1);
            aoff[mt] = (uint32_t)(row * RSTRIDE + 16 * ((lane >> 4) & 1));
        }
#pragma unroll
        for (int ntp = 0; ntp < 4; ntp++) {
            int row = wn * 64 + ntp * 16 + ((lane >> 4) & 1) * 8 + (lane & 7);
            boff[ntp] = (uint32_t)(row * RSTRIDE + 16 * ((lane >> 3) & 1));
        }

        float acc[2][8][4];
#pragma unroll
        for (int mt = 0; mt < 2; mt++)
#pragma unroll
            for (int nt = 0; nt < 8; nt++)
#pragma unroll
                for (int e = 0; e < 4; e++) acc[mt][nt][e] = 0.f;

        for (int c = 0; c < NC; c++) {
            const int s = c & 1;
            const uint32_t aA = sb + SM_RING + s * STAGE_BYTES;
            const uint32_t aB = aA + STAGE_A;
            mbar_wait(sb + s * 16, (c >> 1) & 1);                  // wait full

#pragma unroll
            for (int ks = 0; ks < 4; ks++) {
                uint32_t a0[2][4], a1[2][4], b0[8][2], b1[8][2];
#pragma unroll
                for (int mt = 0; mt < 2; mt++) {
                    LDSM4(a0[mt], aA + 0 * A_PL + ks * 32 + aoff[mt]);
                    LDSM4(a1[mt], aA + 1 * A_PL + ks * 32 + aoff[mt]);
                }
#pragma unroll
                for (int ntp = 0; ntp < 4; ntp++) {
                    uint32_t t4[4];
                    LDSM4(t4, aB + 0 * B_PL + ks * 32 + boff[ntp]);
                    b0[2 * ntp][0] = t4[0]; b0[2 * ntp][1] = t4[1];
                    b0[2 * ntp + 1][0] = t4[2]; b0[2 * ntp + 1][1] = t4[3];
                }
                // q00: x0*w0 (b1 LDSM latency hides under these)
#pragma unroll
                for (int mt = 0; mt < 2; mt++)
#pragma unroll
                    for (int nt = 0; nt < 8; nt++)
                        MMA16816(acc[mt][nt], a0[mt], b0[nt]);
#pragma unroll
                for (int ntp = 0; ntp < 4; ntp++) {
                    uint32_t t4[4];
                    LDSM4(t4, aB + 1 * B_PL + ks * 32 + boff[ntp]);
                    b1[2 * ntp][0] = t4[0]; b1[2 * ntp][1] = t4[1];
                    b1[2 * ntp + 1][0] = t4[2]; b1[2 * ntp + 1][1] = t4[3];
                }
                // q10: x1*w0
#pragma unroll
                for (int mt = 0; mt < 2; mt++)
#pragma unroll
                    for (int nt = 0; nt < 8; nt++)
                        MMA16816(acc[mt][nt], a1[mt], b0[nt]);
                // q01: x0*w1
#pragma unroll
                for (int mt = 0; mt < 2; mt++)
#pragma unroll
                    for (int nt = 0; nt < 8; nt++)
                        MMA16816(acc[mt][nt], a0[mt], b1[nt]);
            }
            mbar_arrive(sb + s * 16 + 8);                          // arrive empty
        }
    }
    __syncthreads();   // all: ring dead, safe to reuse

    float* acc_s = (float*)(smem + SM_RING);   // [TM][AS]
    float* su    = acc_s + TM * AS;            // [TM][US]

    if (wid < 4) {
        const int wm = wid >> 1;
        const int wn = wid & 1;
        // NOTE: recompute mapping constants cheaply (registers from loop scope gone)
        // stage accumulators — but acc lives only in the consumer branch above.
        // To keep acc in scope we must stage inside that branch; restructure:
    }
    // --- staging must happen where acc is in scope; done via second branch ---
    // (see consumer branch below — restructured into a single pass)

    // Producers store their u stash
    if (wid >= 4) {
        const int ptid = tid - NCONS_THREADS;
        float* srow = su + ptid * US;
#pragma unroll
        for (int e = 0; e < 64; e++) srow[e] = ureg[e];
    }
    __syncthreads();

    // ---- per-token epilogue ----
    if (tid < TM) {
        const int m = m0 + tid;
        float* row = acc_s + tid * AS;
        const float* urow = su + tid * US;

        float v1 = -INFINITY, v2 = -INFINITY;
        int i1 = 0, i2 = 0;
        for (int e = 0; e < NEXP; e++) {
            float lg = row[e] * INVSCALE + rb[e];
            float nz = row[NEXP + e] * INVSCALE + nb[e];
            float sp = fmaxf(nz, 0.f) + log1pf(expf(-fabsf(nz)));
            float nv = lg + sp * urow[e];
            if (nv > v1) { v2 = v1; i2 = i1; v1 = nv; i1 = e; }
            else if (nv > v2) { v2 = nv; i2 = e; }
        }
        float e2 = expf(v2 - v1);
        float den = 1.f + e2;
        float p1 = 1.f / den;
        float p2 = e2 / den;

        for (int e = 0; e < NEXP; e++) row[e] = 0.f;
        row[i1] = p1;
        row[i2] = p2;

        float* oid = out + (size_t)M * NEXP;
        oid[(size_t)m * 2 + 0] = (float)i1;
        oid[(size_t)m * 2 + 1] = (float)i2;
    }
    __syncthreads();

    // coalesced probability writeback
    for (int t = tid; t < TM * (NEXP / 4); t += NTHREADS) {
        int r = t >> 4;
        int c4 = (t & 15) * 4;
        float4 v = make_float4(acc_s[r * AS + c4 + 0],
                               acc_s[r * AS + c4 + 1],
                               acc_s[r * AS + c4 + 2],
                               acc_s[r * AS + c4 + 3]);
        *(float4*)(out + (size_t)(m0 + r) * NEXP + c4) = v;
    }
}

// The acc-staging problem above: acc must be staged inside the consumer branch.
// The kernel above was restructured at authoring time; the actual staging is
// performed here via a trick: consumers re-enter a staging block guarded by wid<4
// BEFORE the first __syncthreads. To keep the code correct and simple, the
// consumer branch ends with staging (duplicated below in the real definition).
// --- The definition above is replaced by the corrected one at compile time. ---

extern "C" void kernel_launch(void* const* d_in, const int* in_sizes, int n_in,
                              void* d_out, int out_size);

// ===== corrected kernel (acc staged inside consumer branch, pre-sync) =====
__global__ __launch_bounds__(NTHREADS, 2)
void router_hmma_kernel2(const float* __restrict__ x,
                         const float* __restrict__ rw,
                         const float* __restrict__ rb,
                         const float* __restrict__ nw,
                         const float* __restrict__ nb,
                         const float* __restrict__ u,
                         float* __restrict__ out,
                         int M)
{
    const int tid  = threadIdx.x;
    const int wid  = tid >> 5;
    const int lane = tid & 31;
    const int m0   = blockIdx.x * TM;
    const uint32_t sb = smem_u32(smem);

    if (tid == 0) {
#pragma unroll
        for (int s = 0; s < STAGES; s++) {
            mbar_init(sb + s * 16, NPROD);
            mbar_init(sb + s * 16 + 8, NCONS_THREADS);
        }
    }
    __syncthreads();

    float* acc_s = (float*)(smem + SM_RING);
    float* su    = acc_s + TM * AS;
    float ureg[64];

    if (wid >= 4) {
        // ================= PRODUCER =================
        const int ptid = tid - NCONS_THREADS;
        float4 av[16];
        for (int c = 0; c < NC; c++) {
            const int s = c & 1;
            const uint32_t aA = sb + SM_RING + s * STAGE_BYTES;
            mbar_wait(sb + s * 16 + 8, ((c >> 1) & 1) ^ 1);

#pragma unroll
            for (int i = 0; i < 16; i++) {
                int q = ptid + i * NPROD;
                int row = q >> 4, kq = q & 15;
                av[i] = *(const float4*)(x + (size_t)(m0 + row) * DDIM + c * KC + kq * 4);
            }
#pragma unroll
            for (int i = 0; i < 16; i++) {
                int q = ptid + i * NPROD;
                int row = q >> 4, kq = q & 15;
                uint32_t p0a, p1a, p0b, p1b;
                split2(av[i].x, av[i].y, p0a, p1a);
                split2(av[i].z, av[i].w, p0b, p1b);
                uint32_t base = (aA - sb) + row * RSTRIDE + kq * 8;
                *(uint2*)(smem + base + 0 * A_PL) = make_uint2(p0a, p0b);
                *(uint2*)(smem + base + 1 * A_PL) = make_uint2(p1a, p1b);
            }
            const uint32_t bB = (aA - sb) + STAGE_A;
#pragma unroll
            for (int h = 0; h < 2; h++) {
                float4 wv[16];
#pragma unroll
                for (int i = 0; i < 16; i++) {
                    int q = ptid + (h * 16 + i) * NPROD;
                    int row = q >> 4, kq = q & 15;
                    const float* wsrc = (row < NEXP)
                        ? (rw + (size_t)row * DDIM)
                        : (nw + (size_t)(row - NEXP) * DDIM);
                    wv[i] = *(const float4*)(wsrc + c * KC + kq * 4);
                }
#pragma unroll
                for (int i = 0; i < 16; i++) {
                    int q = ptid + (h * 16 + i) * NPROD;
                    int row = q >> 4, kq = q & 15;
                    uint32_t p0a, p1a, p0b, p1b;
                    split2(wv[i].x * WSCALE, wv[i].y * WSCALE, p0a, p1a);
                    split2(wv[i].z * WSCALE, wv[i].w * WSCALE, p0b, p1b);
                    uint32_t base = bB + row * RSTRIDE + kq * 8;
                    *(uint2*)(smem + base + 0 * B_PL) = make_uint2(p0a, p0b);
                    *(uint2*)(smem + base + 1 * B_PL) = make_uint2(p1a, p1b);
                }
            }
            mbar_arrive(sb + s * 16);
        }
        {
            const float* ur = u + (size_t)(m0 + ptid) * NEXP;
#pragma unroll
            for (int e = 0; e < 64; e++) ureg[e] = ur[e];
        }
    } else {
        // ================= CONSUMER =================
        const int wm = wid >> 1;
        const int wn = wid & 1;

        uint32_t aoff[2], boff[4];
#pragma unroll
        for (int mt = 0; mt < 2; mt++) {
            int row = wm * 32 + mt * 16 + (lane & 7) + 8 * ((lane >> 3) & 1);
            aoff[mt] = (uint32_t)(row * RSTRIDE + 16 * ((lane >> 4) & 1));
        }
#pragma unroll
        for (int ntp = 0; ntp < 4; ntp++) {
            int row = wn * 64 + ntp * 16 + ((lane >> 4) & 1) * 8 + (lane & 7);
            boff[ntp] = (uint32_t)(row * RSTRIDE + 16 * ((lane >> 3) & 1));
        }

        float acc[2][8][4];
#pragma unroll
        for (int mt = 0; mt < 2; mt++)
#pragma unroll
            for (int nt = 0; nt < 8; nt++)
#pragma unroll
                for (int e = 0; e < 4; e++) acc[mt][nt][e] = 0.f;

        for (int c = 0; c < NC; c++) {
            const int s = c & 1;
            const uint32_t aA = sb + SM_RING + s * STAGE_BYTES;
            const uint32_t aB = aA + STAGE_A;
            mbar_wait(sb + s * 16, (c >> 1) & 1);

#pragma unroll
            for (int ks = 0; ks < 4; ks++) {
                uint32_t a0[2][4], a1[2][4], b0[8][2], b1[8][2];
#pragma unroll
                for (int mt = 0; mt < 2; mt++) {
                    LDSM4(a0[mt], aA + 0 * A_PL + ks * 32 + aoff[mt]);
                    LDSM4(a1[mt], aA + 1 * A_PL + ks * 32 + aoff[mt]);
                }
#pragma unroll
                for (int ntp = 0; ntp < 4; ntp++) {
                    uint32_t t4[4];
                    LDSM4(t4, aB + 0 * B_PL + ks * 32 + boff[ntp]);
                    b0[2 * ntp][0] = t4[0]; b0[2 * ntp][1] = t4[1];
                    b0[2 * ntp + 1][0] = t4[2]; b0[2 * ntp + 1][1] = t4[3];
                }
#pragma unroll
                for (int mt = 0; mt < 2; mt++)
#pragma unroll
                    for (int nt = 0; nt < 8; nt++)
                        MMA16816(acc[mt][nt], a0[mt], b0[nt]);
#pragma unroll
                for (int ntp = 0; ntp < 4; ntp++) {
                    uint32_t t4[4];
                    LDSM4(t4, aB + 1 * B_PL + ks * 32 + boff[ntp]);
                    b1[2 * ntp][0] = t4[0]; b1[2 * ntp][1] = t4[1];
                    b1[2 * ntp + 1][0] = t4[2]; b1[2 * ntp + 1][1] = t4[3];
                }
#pragma unroll
                for (int mt = 0; mt < 2; mt++)
#pragma unroll
                    for (int nt = 0; nt < 8; nt++)
                        MMA16816(acc[mt][nt], a1[mt], b0[nt]);
#pragma unroll
                for (int mt = 0; mt < 2; mt++)
#pragma unroll
                    for (int nt = 0; nt < 8; nt++)
                        MMA16816(acc[mt][nt], a0[mt], b1[nt]);
            }
            mbar_arrive(sb + s * 16 + 8);
        }

        __syncthreads();   // join producers; ring now dead
#pragma unroll
        for (int mt = 0; mt < 2; mt++)
#pragma unroll
            for (int nt = 0; nt < 8; nt++) {
                int r   = wm * 32 + mt * 16 + (lane >> 2);
                int col = wn * 64 + nt * 8 + (lane & 3) * 2;
                acc_s[r * AS + col]           = acc[mt][nt][0];
                acc_s[r * AS + col + 1]       = acc[mt][nt][1];
                acc_s[(r + 8) * AS + col]     = acc[mt][nt][2];
                acc_s[(r + 8) * AS + col + 1] = acc[mt][nt][3];
            }
    }
    if (wid >= 4) {
        __syncthreads();   // matching join
        const int ptid = tid - NCONS_THREADS;
        float* srow = su + ptid * US;
#pragma unroll
        for (int e = 0; e < 64; e++) srow[e] = ureg[e];
    }
    __syncthreads();

    if (tid < TM) {
        const int m = m0 + tid;
        float* row = acc_s + tid * AS;
        const float* urow = su + tid * US;

        float v1 = -INFINITY, v2 = -INFINITY;
        int i1 = 0, i2 = 0;
        for (int e = 0; e < NEXP; e++) {
            float lg = row[e] * INVSCALE + rb[e];
            float nz = row[NEXP + e] * INVSCALE + nb[e];
            float sp = fmaxf(nz, 0.f) + log1pf(expf(-fabsf(nz)));
            float nv = lg + sp * urow[e];
            if (nv > v1) { v2 = v1; i2 = i1; v1 = nv; i1 = e; }
            else if (nv > v2) { v2 = nv; i2 = e; }
        }
        float e2 = expf(v2 - v1);
        float den = 1.f + e2;
        float p1 = 1.f / den;
        float p2 = e2 / den;

        for (int e = 0; e < NEXP; e++) row[e] = 0.f;
        row[i1] = p1;
        row[i2] = p2;

        float* oid = out + (size_t)M * NEXP;
        oid[(size_t)m * 2 + 0] = (float)i1;
        oid[(size_t)m * 2 + 1] = (float)i2;
    }
    __syncthreads();

    for (int t = tid; t < TM * (NEXP / 4); t += NTHREADS) {
        int r = t >> 4;
        int c4 = (t & 15) * 4;
        float4 v = make_float4(acc_s[r * AS + c4 + 0],
                               acc_s[r * AS + c4 + 1],
                               acc_s[r * AS + c4 + 2],
                               acc_s[r * AS + c4 + 3]);
        *(float4*)(out + (size_t)(m0 + r) * NEXP + c4) = v;
    }
}

extern "C" void kernel_launch(void* const* d_in, const int* in_sizes, int n_in,
                              void* d_out, int out_size)
{
    const float* x  = (const float*)d_in[0];
    const float* rw = (const float*)d_in[1];
    const float* rb = (const float*)d_in[2];
    const float* nw = (const float*)d_in[3];
    const float* nb = (const float*)d_in[4];
    const float* u  = (const float*)d_in[5];

    const int M = in_sizes[0] / DDIM;  // 16384

    static bool attr_set = false;
    if (!attr_set) {
        cudaFuncSetAttribute(router_hmma_kernel2,
                             cudaFuncAttributeMaxDynamicSharedMemorySize,
                             SMEM_BYTES);
        attr_set = true;
    }

    router_hmma_kernel2<<<M / TM, NTHREADS, SMEM_BYTES>>>(x, rw, rb, nw, nb, u,
                                                          (float*)d_out, M);
}